// round 9
// baseline (speedup 1.0000x reference)
#include <cuda_runtime.h>
#include <math.h>

#define NH   64
#define NINP 128
#define NHID 512
#define NOUT 256
#define NSM  4
#define TINYF 1e-14f

// ---------------- scratch (device globals; no allocations allowed) ----------
__device__ float g_h1pre[NH * NHID];          // w1 @ sub, pre-GN
__device__ float g_partial[NSM * NH * NOUT];  // softmax per (s,h), [s][h][o]
__device__ float g_scalar_ho[NH * NOUT];      // ws row sums, [h][o]

// ---------------- reduction helpers -----------------------------------------
__device__ __forceinline__ float warpSum(float v) {
#pragma unroll
    for (int o = 16; o; o >>= 1) v += __shfl_xor_sync(0xffffffffu, v, o);
    return v;
}
__device__ __forceinline__ float warpMax(float v) {
#pragma unroll
    for (int o = 16; o; o >>= 1) v = fmaxf(v, __shfl_xor_sync(0xffffffffu, v, o));
    return v;
}
__device__ __forceinline__ float warpProd(float v) {
#pragma unroll
    for (int o = 16; o; o >>= 1) v *= __shfl_xor_sync(0xffffffffu, v, o);
    return v;
}
template <int NW>
__device__ __forceinline__ float blockSum(float v, float* red) {
    int w = threadIdx.x >> 5, lane = threadIdx.x & 31;
    v = warpSum(v);
    __syncthreads();
    if (lane == 0) red[w] = v;
    __syncthreads();
    float r = (lane < NW) ? red[lane] : 0.f;
    return warpSum(r);
}
template <int NW>
__device__ __forceinline__ float blockMax(float v, float* red) {
    int w = threadIdx.x >> 5, lane = threadIdx.x & 31;
    v = warpMax(v);
    __syncthreads();
    if (lane == 0) red[w] = v;
    __syncthreads();
    float r = (lane < NW) ? red[lane] : -3.4e38f;
    return warpMax(r);
}

// ---------------- kA1: h1pre = w1 @ (x @ qw_h); block = (h, quarter) --------
__global__ __launch_bounds__(512) void kA1(
    const float* __restrict__ x, const float* __restrict__ qw,
    const float* __restrict__ w1)
{
    int h = blockIdx.x >> 2, c = blockIdx.x & 3;
    __shared__ __align__(16) float qws[NINP];
    __shared__ __align__(16) float sub[NINP];
    int tid = threadIdx.x, w = tid >> 5, lane = tid & 31;

    if (tid < NINP) qws[tid] = qw[h * NINP + tid];
    __syncthreads();

    // sub[r] = dot(x[r,:], qw[h,:]); 16 warps x 8 rows (x is L2-resident)
    float4 qv = ((const float4*)qws)[lane];
#pragma unroll
    for (int rr = 0; rr < 8; ++rr) {
        int r = w * 8 + rr;
        float4 xv = ((const float4*)(x + (size_t)r * NINP))[lane];
        float p = xv.x * qv.x + xv.y * qv.y + xv.z * qv.z + xv.w * qv.w;
        p = warpSum(p);
        if (lane == 0) sub[r] = p;
    }
    __syncthreads();

    // 128 rows of w1 for this (h, c); warp-per-row, 2 rows in flight
    float4 sv = ((const float4*)sub)[lane];
    const float* w1h = w1 + ((size_t)h * NHID + c * 128) * NINP;
    float* dst = g_h1pre + h * NHID + c * 128;
#pragma unroll 1
    for (int rr = 0; rr < 8; rr += 2) {
        int r0 = w * 8 + rr;
        float4 a0 = ((const float4*)(w1h + (size_t)r0 * NINP))[lane];
        float4 a1 = ((const float4*)(w1h + (size_t)(r0 + 1) * NINP))[lane];
        float p0 = a0.x * sv.x + a0.y * sv.y + a0.z * sv.z + a0.w * sv.w;
        float p1 = a1.x * sv.x + a1.y * sv.y + a1.z * sv.z + a1.w * sv.w;
        p0 = warpSum(p0);
        p1 = warpSum(p1);
        if (lane == 0) { dst[r0] = p0; dst[r0 + 1] = p1; }
    }
}

// ---------------- kBC: kB with inline GN/softplus (blocks 0..255)
//                  + kC ws row sums (blocks 256..383) ------------------------
__global__ __launch_bounds__(256) void kBC(
    const float* __restrict__ w2, const float* __restrict__ g2,
    const float* __restrict__ b2, const float* __restrict__ ws,
    const float* __restrict__ g1, const float* __restrict__ b1)
{
    int tid = threadIdx.x, w = tid >> 5, lane = tid & 31;

    if (blockIdx.x >= NSM * NH) {
        // ----- kC: scalar[h][o] = sum_i ws[h,o,i] -----
        int wg = (blockIdx.x - NSM * NH) * 8 + w;   // 1024 warps, 16 rows each
#pragma unroll 1
        for (int i = 0; i < 16; ++i) {
            int row = wg * 16 + i;                  // row = h*256 + o
            const float4* p = (const float4*)(ws + (size_t)row * NOUT);
            float a = 0.f;
#pragma unroll
            for (int j = 0; j < 2; ++j) {
                float4 v = p[j * 32 + lane];
                a += v.x + v.y + v.z + v.w;
            }
            a = warpSum(a);
            if (lane == 0) g_scalar_ho[row] = a;
        }
        return;
    }

    // ----- kB: GN1+softplus(h1pre) inline, then z = w2·h1, GN2, softmax -----
    int sh = blockIdx.x;
    int h = sh & 63;
    __shared__ __align__(16) float h1s[NHID];
    __shared__ float zs[NOUT];
    __shared__ float red[8];

    // load pre-activation, GroupNorm over 512 + softplus (redundant per s; cheap)
    float v0 = g_h1pre[h * NHID + tid];
    float v1 = g_h1pre[h * NHID + 256 + tid];
    float s1 = blockSum<8>(v0 + v1, red);
    float s2 = blockSum<8>(v0 * v0 + v1 * v1, red);
    float mu = s1 * (1.f / NHID);
    float var = s2 * (1.f / NHID) - mu * mu;
    float rs = rsqrtf(var + 1e-5f);
    {
        float zn0 = (v0 - mu) * rs * g1[h * NHID + tid] + b1[h * NHID + tid];
        float zn1 = (v1 - mu) * rs * g1[h * NHID + 256 + tid] + b1[h * NHID + 256 + tid];
        h1s[tid]       = fmaxf(zn0, 0.f) + log1pf(expf(-fabsf(zn0)));
        h1s[tid + 256] = fmaxf(zn1, 0.f) + log1pf(expf(-fabsf(zn1)));
    }
    __syncthreads();

    float4 hv[4];
#pragma unroll
    for (int j = 0; j < 4; ++j) hv[j] = ((const float4*)h1s)[j * 32 + lane];

    const float* w2b = w2 + (size_t)sh * NOUT * NHID;
#pragma unroll 1
    for (int rr = 0; rr < 32; rr += 2) {
        int r0 = w * 32 + rr;
        const float4* p0 = (const float4*)(w2b + (size_t)r0 * NHID);
        const float4* p1 = (const float4*)(w2b + (size_t)(r0 + 1) * NHID);
        float a0 = 0.f, a1 = 0.f;
#pragma unroll
        for (int j = 0; j < 4; ++j) {
            float4 u0 = p0[j * 32 + lane];
            float4 u1 = p1[j * 32 + lane];
            a0 += u0.x * hv[j].x + u0.y * hv[j].y + u0.z * hv[j].z + u0.w * hv[j].w;
            a1 += u1.x * hv[j].x + u1.y * hv[j].y + u1.z * hv[j].z + u1.w * hv[j].w;
        }
        a0 = warpSum(a0);
        a1 = warpSum(a1);
        if (lane == 0) { zs[r0] = a0; zs[r0 + 1] = a1; }
    }
    __syncthreads();

    float z = zs[tid];
    float t1 = blockSum<8>(z, red);
    float t2 = blockSum<8>(z * z, red);
    float mu2 = t1 * (1.f / NOUT);
    float var2 = t2 * (1.f / NOUT) - mu2 * mu2;
    float zn = (z - mu2) * rsqrtf(var2 + 1e-5f) * g2[sh * NOUT + tid] + b2[sh * NOUT + tid];

    float m = blockMax<8>(zn, red);
    float e = expf(zn - m);
    float se = blockSum<8>(e, red);
    g_partial[sh * NOUT + tid] = e / se;   // [s][h][o], coalesced
}

// ---------------- kTail: block per head — out_sm, last_prod, gate, outputs --
__global__ __launch_bounds__(256) void kTail(
    const float* __restrict__ last, const float* __restrict__ woo,
    float* __restrict__ out)
{
    int h = blockIdx.x;
    int tid = threadIdx.x, w = tid >> 5, lane = tid & 31;
    __shared__ float osm[NOUT];
    __shared__ float lp[NOUT];
    __shared__ float red[8];

    // out_sm[o] for this head: sum over s of softmax partials (coalesced)
    float s = 0.f;
#pragma unroll
    for (int s4 = 0; s4 < NSM; ++s4) s += g_partial[(s4 * NH + h) * NOUT + tid];
    osm[tid] = s;

    // last_prod[o] = prod over heads; warp per o, coalesced loads (L2-resident)
#pragma unroll 1
    for (int i = 0; i < 32; ++i) {
        int o = w * 32 + i;
        float p = last[o * NH + lane] * last[o * NH + 32 + lane];
        p = warpProd(p);
        if (lane == 0) lp[o] = p;
    }
    __syncthreads();

    // gate logit for this head
    float term = woo[(size_t)h * 2 * NOUT + tid] * lp[tid]
               + woo[(size_t)h * 2 * NOUT + NOUT + tid] * osm[tid];
    float gl = blockSum<8>(term, red);
    float onoff = 1.f / (1.f + expf(-gl));

    // final outputs (strided 4B stores; tiny)
    float v = onoff * osm[tid];
    out[tid * NH + h] = fmaxf(v, TINYF);
    float v2 = v * g_scalar_ho[h * NOUT + tid];
    out[NOUT * NH + tid * NH + h] = (fabsf(v2) <= TINYF) ? TINYF : v2;
}

// ---------------- launch -----------------------------------------------------
extern "C" void kernel_launch(void* const* d_in, const int* in_sizes, int n_in,
                              void* d_out, int out_size)
{
    const float* x    = (const float*)d_in[0];
    const float* last = (const float*)d_in[1];
    const float* qw   = (const float*)d_in[2];
    const float* w1   = (const float*)d_in[3];
    const float* g1   = (const float*)d_in[4];
    const float* b1   = (const float*)d_in[5];
    const float* w2   = (const float*)d_in[6];
    const float* g2   = (const float*)d_in[7];
    const float* b2   = (const float*)d_in[8];
    const float* ws   = (const float*)d_in[9];
    const float* woo  = (const float*)d_in[10];
    float* out = (float*)d_out;

    kA1<<<NH * 4, 512>>>(x, qw, w1);
    kBC<<<NSM * NH + 128, 256>>>(w2, g2, b2, ws, g1, b1);
    kTail<<<NH, 256>>>(last, woo, out);
}

// round 11
// speedup vs baseline: 1.0667x; 1.0667x over previous
#include <cuda_runtime.h>
#include <math.h>

#define NH   64
#define NINP 128
#define NHID 512
#define NOUT 256
#define NSM  4
#define TINYF 1e-14f

// ---------------- scratch (device globals; no allocations allowed) ----------
__device__ float g_h1pre[NH * NHID];          // w1 @ sub, pre-GN
__device__ float g_h1[NH * NHID];             // softplus(GN1(h1pre))
__device__ float g_z[NSM * NH * NOUT];        // w2 @ h1, pre-GN2, [s][h][o]
__device__ float g_scalar_ho[NH * NOUT];      // ws row sums, [h][o]

// ---------------- reduction helpers -----------------------------------------
__device__ __forceinline__ float warpSum(float v) {
#pragma unroll
    for (int o = 16; o; o >>= 1) v += __shfl_xor_sync(0xffffffffu, v, o);
    return v;
}
__device__ __forceinline__ float warpMax(float v) {
#pragma unroll
    for (int o = 16; o; o >>= 1) v = fmaxf(v, __shfl_xor_sync(0xffffffffu, v, o));
    return v;
}
__device__ __forceinline__ float warpProd(float v) {
#pragma unroll
    for (int o = 16; o; o >>= 1) v *= __shfl_xor_sync(0xffffffffu, v, o);
    return v;
}
template <int NW>
__device__ __forceinline__ float blockSum(float v, float* red) {
    int w = threadIdx.x >> 5, lane = threadIdx.x & 31;
    v = warpSum(v);
    __syncthreads();
    if (lane == 0) red[w] = v;
    __syncthreads();
    float r = (lane < NW) ? red[lane] : 0.f;
    return warpSum(r);
}
template <int NW>
__device__ __forceinline__ float blockMax(float v, float* red) {
    int w = threadIdx.x >> 5, lane = threadIdx.x & 31;
    v = warpMax(v);
    __syncthreads();
    if (lane == 0) red[w] = v;
    __syncthreads();
    float r = (lane < NW) ? red[lane] : -3.4e38f;
    return warpMax(r);
}

// ---------------- kA1: h1pre = w1 @ (x @ qw_h); block = (h, quarter) --------
__global__ __launch_bounds__(512) void kA1(
    const float* __restrict__ x, const float* __restrict__ qw,
    const float* __restrict__ w1)
{
    int h = blockIdx.x >> 2, c = blockIdx.x & 3;
    __shared__ __align__(16) float qws[NINP];
    __shared__ __align__(16) float sub[NINP];
    int tid = threadIdx.x, w = tid >> 5, lane = tid & 31;

    if (tid < NINP) qws[tid] = qw[h * NINP + tid];
    __syncthreads();

    // sub[r] = dot(x[r,:], qw[h,:]); 16 warps x 8 rows (x is L2-resident)
    float4 qv = ((const float4*)qws)[lane];
#pragma unroll
    for (int rr = 0; rr < 8; ++rr) {
        int r = w * 8 + rr;
        float4 xv = ((const float4*)(x + (size_t)r * NINP))[lane];
        float p = xv.x * qv.x + xv.y * qv.y + xv.z * qv.z + xv.w * qv.w;
        p = warpSum(p);
        if (lane == 0) sub[r] = p;
    }
    __syncthreads();

    // 128 rows of w1 for this (h, c); warp-per-row, 2 rows in flight
    float4 sv = ((const float4*)sub)[lane];
    const float* w1h = w1 + ((size_t)h * NHID + c * 128) * NINP;
    float* dst = g_h1pre + h * NHID + c * 128;
#pragma unroll 1
    for (int rr = 0; rr < 8; rr += 2) {
        int r0 = w * 8 + rr;
        float4 a0 = ((const float4*)(w1h + (size_t)r0 * NINP))[lane];
        float4 a1 = ((const float4*)(w1h + (size_t)(r0 + 1) * NINP))[lane];
        float p0 = a0.x * sv.x + a0.y * sv.y + a0.z * sv.z + a0.w * sv.w;
        float p1 = a1.x * sv.x + a1.y * sv.y + a1.z * sv.z + a1.w * sv.w;
        p0 = warpSum(p0);
        p1 = warpSum(p1);
        if (lane == 0) { dst[r0] = p0; dst[r0 + 1] = p1; }
    }
}

// ---------------- kA2: GroupNorm + softplus over NHID; block per head -------
__global__ __launch_bounds__(512) void kA2(
    const float* __restrict__ g1, const float* __restrict__ b1)
{
    int h = blockIdx.x, tid = threadIdx.x;
    __shared__ float red[16];
    float v = g_h1pre[h * NHID + tid];
    float s1 = blockSum<16>(v, red);
    float s2 = blockSum<16>(v * v, red);
    float mu = s1 * (1.f / NHID);
    float var = s2 * (1.f / NHID) - mu * mu;
    float zn = (v - mu) * rsqrtf(var + 1e-5f) * g1[h * NHID + tid] + b1[h * NHID + tid];
    g_h1[h * NHID + tid] = fmaxf(zn, 0.f) + log1pf(expf(-fabsf(zn)));
}

// ---------------- kZC: z = w2·h1 (blocks 0..1023, 64 rows each)
//                  + ws row sums (blocks 1024..1151) -------------------------
__global__ __launch_bounds__(256) void kZC(
    const float* __restrict__ w2, const float* __restrict__ ws)
{
    int tid = threadIdx.x, w = tid >> 5, lane = tid & 31;

    if (blockIdx.x >= NSM * NH * 4) {
        // ----- ws: scalar[h][o] = sum_i ws[h,o,i] -----
        int wg = (blockIdx.x - NSM * NH * 4) * 8 + w;   // 1024 warps, 16 rows each
#pragma unroll 1
        for (int i = 0; i < 16; ++i) {
            int row = wg * 16 + i;                      // row = h*256 + o
            const float4* p = (const float4*)(ws + (size_t)row * NOUT);
            float a = 0.f;
#pragma unroll
            for (int j = 0; j < 2; ++j) {
                float4 v = p[j * 32 + lane];
                a += v.x + v.y + v.z + v.w;
            }
            a = warpSum(a);
            if (lane == 0) g_scalar_ho[row] = a;
        }
        return;
    }

    // ----- z: block = (sh, quarter); 8 warps x 8 rows of 512 ------
    int sh = blockIdx.x >> 2;       // s*64 + h
    int q  = blockIdx.x & 3;        // quarter of the 256 output rows
    int h  = sh & 63;
    __shared__ __align__(16) float h1s[NHID];

    h1s[tid]       = g_h1[h * NHID + tid];
    h1s[tid + 256] = g_h1[h * NHID + tid + 256];
    __syncthreads();

    float4 hv[4];
#pragma unroll
    for (int j = 0; j < 4; ++j) hv[j] = ((const float4*)h1s)[j * 32 + lane];

    const float* w2b = w2 + (size_t)sh * NOUT * NHID;
    float* zout = g_z + (size_t)sh * NOUT;
#pragma unroll 1
    for (int rr = 0; rr < 8; rr += 2) {
        int r0 = q * 64 + w * 8 + rr;
        const float4* p0 = (const float4*)(w2b + (size_t)r0 * NHID);
        const float4* p1 = (const float4*)(w2b + (size_t)(r0 + 1) * NHID);
        float a0 = 0.f, a1 = 0.f;
#pragma unroll
        for (int j = 0; j < 4; ++j) {
            float4 u0 = p0[j * 32 + lane];
            float4 u1 = p1[j * 32 + lane];
            a0 += u0.x * hv[j].x + u0.y * hv[j].y + u0.z * hv[j].z + u0.w * hv[j].w;
            a1 += u1.x * hv[j].x + u1.y * hv[j].y + u1.z * hv[j].z + u1.w * hv[j].w;
        }
        a0 = warpSum(a0);
        a1 = warpSum(a1);
        if (lane == 0) { zout[r0] = a0; zout[r0 + 1] = a1; }
    }
}

// ---------------- kTail2: block per head — GN2+softmax (4 s), out_sm,
//                  last_prod, gate, final outputs ----------------------------
__global__ __launch_bounds__(256) void kTail2(
    const float* __restrict__ g2, const float* __restrict__ b2,
    const float* __restrict__ last, const float* __restrict__ woo,
    float* __restrict__ out)
{
    int h = blockIdx.x;
    int tid = threadIdx.x, w = tid >> 5, lane = tid & 31;
    __shared__ float lp[NOUT];
    __shared__ float red[8];

    // last_prod[o] = prod over 64 heads; warp per o (coalesced, L2-resident)
#pragma unroll 1
    for (int i = 0; i < 32; ++i) {
        int o = w * 32 + i;
        float p = last[o * NH + lane] * last[o * NH + 32 + lane];
        p = warpProd(p);
        if (lane == 0) lp[o] = p;
    }

    // GN2 + softmax per s, accumulate out_sm[o] for this head
    float osm = 0.f;
#pragma unroll 1
    for (int s4 = 0; s4 < NSM; ++s4) {
        int sh = s4 * NH + h;
        float z = g_z[(size_t)sh * NOUT + tid];
        float s1 = blockSum<8>(z, red);
        float s2 = blockSum<8>(z * z, red);
        float mu = s1 * (1.f / NOUT);
        float var = s2 * (1.f / NOUT) - mu * mu;
        float zn = (z - mu) * rsqrtf(var + 1e-5f) * g2[sh * NOUT + tid] + b2[sh * NOUT + tid];
        float m = blockMax<8>(zn, red);
        float e = expf(zn - m);
        float se = blockSum<8>(e, red);
        osm += e / se;
    }
    // barriers inside the s-loop have already made lp[] visible block-wide

    // gate logit for this head
    float term = woo[(size_t)h * 2 * NOUT + tid] * lp[tid]
               + woo[(size_t)h * 2 * NOUT + NOUT + tid] * osm;
    float gl = blockSum<8>(term, red);
    float onoff = 1.f / (1.f + expf(-gl));

    // final outputs (strided 4B stores; 128KB total, negligible)
    float v = onoff * osm;
    out[tid * NH + h] = fmaxf(v, TINYF);
    float v2 = v * g_scalar_ho[h * NOUT + tid];
    out[NOUT * NH + tid * NH + h] = (fabsf(v2) <= TINYF) ? TINYF : v2;
}

// ---------------- launch -----------------------------------------------------
extern "C" void kernel_launch(void* const* d_in, const int* in_sizes, int n_in,
                              void* d_out, int out_size)
{
    const float* x    = (const float*)d_in[0];
    const float* last = (const float*)d_in[1];
    const float* qw   = (const float*)d_in[2];
    const float* w1   = (const float*)d_in[3];
    const float* g1   = (const float*)d_in[4];
    const float* b1   = (const float*)d_in[5];
    const float* w2   = (const float*)d_in[6];
    const float* g2   = (const float*)d_in[7];
    const float* b2   = (const float*)d_in[8];
    const float* ws   = (const float*)d_in[9];
    const float* woo  = (const float*)d_in[10];
    float* out = (float*)d_out;

    kA1<<<NH * 4, 512>>>(x, qw, w1);
    kA2<<<NH, 512>>>(g1, b1);
    kZC<<<NSM * NH * 4 + 128, 256>>>(w2, ws);
    kTail2<<<NH, 256>>>(g2, b2, last, woo, out);
}

// round 12
// speedup vs baseline: 1.3788x; 1.2926x over previous
#include <cuda_runtime.h>
#include <math.h>

#define NH   64
#define NINP 128
#define NHID 512
#define NOUT 256
#define NSM  4
#define TINYF 1e-14f

// ---------------- scratch (device globals; no allocations allowed) ----------
__device__ float g_sub[NH * NINP];            // x @ qw_h per head
__device__ float g_h1pre[NH * NHID];          // w1 @ sub, pre-GN
__device__ float g_h1[NH * NHID];             // softplus(GN1(h1pre))
__device__ float g_z[NSM * NH * NOUT];        // w2 @ h1, pre-GN2, [s][h][o]
__device__ float g_partial[NSM * NH * NOUT];  // softmax per (s,h), [s][h][o]
__device__ float g_scalar_ho[NH * NOUT];      // ws row sums, [h][o]
__device__ float g_lp[NOUT];                  // prod over heads of last_out_sm

// ---------------- reduction helpers -----------------------------------------
__device__ __forceinline__ float warpSum(float v) {
#pragma unroll
    for (int o = 16; o; o >>= 1) v += __shfl_xor_sync(0xffffffffu, v, o);
    return v;
}
__device__ __forceinline__ float warpMax(float v) {
#pragma unroll
    for (int o = 16; o; o >>= 1) v = fmaxf(v, __shfl_xor_sync(0xffffffffu, v, o));
    return v;
}
__device__ __forceinline__ float warpProd(float v) {
#pragma unroll
    for (int o = 16; o; o >>= 1) v *= __shfl_xor_sync(0xffffffffu, v, o);
    return v;
}
template <int NW>
__device__ __forceinline__ float blockSum(float v, float* red) {
    int w = threadIdx.x >> 5, lane = threadIdx.x & 31;
    v = warpSum(v);
    __syncthreads();
    if (lane == 0) red[w] = v;
    __syncthreads();
    float r = (lane < NW) ? red[lane] : 0.f;
    return warpSum(r);
}
template <int NW>
__device__ __forceinline__ float blockMax(float v, float* red) {
    int w = threadIdx.x >> 5, lane = threadIdx.x & 31;
    v = warpMax(v);
    __syncthreads();
    if (lane == 0) red[w] = v;
    __syncthreads();
    float r = (lane < NW) ? red[lane] : -3.4e38f;
    return warpMax(r);
}

// ---------------- kA0: sub[h][r] = dot(x[r,:], qw[h,:]); block=(h, rowgroup)
__global__ __launch_bounds__(256) void kA0(
    const float* __restrict__ x, const float* __restrict__ qw)
{
    int h = blockIdx.x >> 2, rg = blockIdx.x & 3;
    __shared__ __align__(16) float qws[NINP];
    int tid = threadIdx.x, w = tid >> 5, lane = tid & 31;

    if (tid < NINP) qws[tid] = qw[h * NINP + tid];
    __syncthreads();

    float4 qv = ((const float4*)qws)[lane];
#pragma unroll
    for (int rr = 0; rr < 4; ++rr) {
        int r = rg * 32 + w * 4 + rr;
        float4 xv = ((const float4*)(x + (size_t)r * NINP))[lane];
        float p = xv.x * qv.x + xv.y * qv.y + xv.z * qv.z + xv.w * qv.w;
        p = warpSum(p);
        if (lane == 0) g_sub[h * NINP + r] = p;
    }
}

// ---------------- kA1: h1pre = w1 @ sub; block = (h, eighth), 64 rows each --
__global__ __launch_bounds__(256) void kA1(const float* __restrict__ w1)
{
    int h = blockIdx.x >> 3, c = blockIdx.x & 7;
    int tid = threadIdx.x, w = tid >> 5, lane = tid & 31;

    // each warp loads the whole 128-float sub vector directly (L2-resident)
    float4 sv = ((const float4*)(g_sub + h * NINP))[lane];

    const float* w1h = w1 + ((size_t)h * NHID + c * 64) * NINP;
    float* dst = g_h1pre + h * NHID + c * 64;
#pragma unroll 1
    for (int rr = 0; rr < 8; rr += 2) {
        int r0 = w * 8 + rr;
        float4 a0 = ((const float4*)(w1h + (size_t)r0 * NINP))[lane];
        float4 a1 = ((const float4*)(w1h + (size_t)(r0 + 1) * NINP))[lane];
        float p0 = a0.x * sv.x + a0.y * sv.y + a0.z * sv.z + a0.w * sv.w;
        float p1 = a1.x * sv.x + a1.y * sv.y + a1.z * sv.z + a1.w * sv.w;
        p0 = warpSum(p0);
        p1 = warpSum(p1);
        if (lane == 0) { dst[r0] = p0; dst[r0 + 1] = p1; }
    }
}

// ---------------- kA2: GN1+softplus (blocks 0..63) + last_prod (64..71) -----
__global__ __launch_bounds__(512) void kA2(
    const float* __restrict__ g1, const float* __restrict__ b1,
    const float* __restrict__ last)
{
    int tid = threadIdx.x, w = tid >> 5, lane = tid & 31;

    if (blockIdx.x >= NH) {
        // last_prod: 8 blocks x 16 warps x 2 o's = 256 outputs
        int b = blockIdx.x - NH;
#pragma unroll
        for (int i = 0; i < 2; ++i) {
            int o = b * 32 + w * 2 + i;
            float p = last[o * NH + lane] * last[o * NH + 32 + lane];
            p = warpProd(p);
            if (lane == 0) g_lp[o] = p;
        }
        return;
    }

    int h = blockIdx.x;
    __shared__ float red[16];
    float v = g_h1pre[h * NHID + tid];
    float s1 = blockSum<16>(v, red);
    float s2 = blockSum<16>(v * v, red);
    float mu = s1 * (1.f / NHID);
    float var = s2 * (1.f / NHID) - mu * mu;
    float zn = (v - mu) * rsqrtf(var + 1e-5f) * g1[h * NHID + tid] + b1[h * NHID + tid];
    g_h1[h * NHID + tid] = fmaxf(zn, 0.f) + log1pf(expf(-fabsf(zn)));
}

// ---------------- kZC: z = w2·h1 (blocks 0..1023, 64 rows each)
//                  + ws row sums (blocks 1024..1151) -------------------------
__global__ __launch_bounds__(256) void kZC(
    const float* __restrict__ w2, const float* __restrict__ ws)
{
    int tid = threadIdx.x, w = tid >> 5, lane = tid & 31;

    if (blockIdx.x >= NSM * NH * 4) {
        // ----- ws: scalar[h][o] = sum_i ws[h,o,i] -----
        int wg = (blockIdx.x - NSM * NH * 4) * 8 + w;   // 1024 warps, 16 rows each
#pragma unroll 1
        for (int i = 0; i < 16; ++i) {
            int row = wg * 16 + i;                      // row = h*256 + o
            const float4* p = (const float4*)(ws + (size_t)row * NOUT);
            float a = 0.f;
#pragma unroll
            for (int j = 0; j < 2; ++j) {
                float4 v = p[j * 32 + lane];
                a += v.x + v.y + v.z + v.w;
            }
            a = warpSum(a);
            if (lane == 0) g_scalar_ho[row] = a;
        }
        return;
    }

    // ----- z: block = (sh, quarter); 8 warps x 8 rows of 512 ------
    int sh = blockIdx.x >> 2;       // s*64 + h
    int q  = blockIdx.x & 3;        // quarter of the 256 output rows
    int h  = sh & 63;

    // each warp loads the full 512-float h1 directly (L2-resident, no barrier)
    float4 hv[4];
#pragma unroll
    for (int j = 0; j < 4; ++j)
        hv[j] = ((const float4*)(g_h1 + h * NHID))[j * 32 + lane];

    const float* w2b = w2 + (size_t)sh * NOUT * NHID;
    float* zout = g_z + (size_t)sh * NOUT;
#pragma unroll 1
    for (int rr = 0; rr < 8; rr += 2) {
        int r0 = q * 64 + w * 8 + rr;
        const float4* p0 = (const float4*)(w2b + (size_t)r0 * NHID);
        const float4* p1 = (const float4*)(w2b + (size_t)(r0 + 1) * NHID);
        float a0 = 0.f, a1 = 0.f;
#pragma unroll
        for (int j = 0; j < 4; ++j) {
            float4 u0 = p0[j * 32 + lane];
            float4 u1 = p1[j * 32 + lane];
            a0 += u0.x * hv[j].x + u0.y * hv[j].y + u0.z * hv[j].z + u0.w * hv[j].w;
            a1 += u1.x * hv[j].x + u1.y * hv[j].y + u1.z * hv[j].z + u1.w * hv[j].w;
        }
        a0 = warpSum(a0);
        a1 = warpSum(a1);
        if (lane == 0) { zout[r0] = a0; zout[r0 + 1] = a1; }
    }
}

// ---------------- kP: GN2 + softmax; block per (s,h) ------------------------
__global__ __launch_bounds__(256) void kP(
    const float* __restrict__ g2, const float* __restrict__ b2)
{
    int sh = blockIdx.x, tid = threadIdx.x;
    __shared__ float red[8];

    float z = g_z[(size_t)sh * NOUT + tid];
    float s1 = blockSum<8>(z, red);
    float s2 = blockSum<8>(z * z, red);
    float mu = s1 * (1.f / NOUT);
    float var = s2 * (1.f / NOUT) - mu * mu;
    float zn = (z - mu) * rsqrtf(var + 1e-5f) * g2[sh * NOUT + tid] + b2[sh * NOUT + tid];
    float m = blockMax<8>(zn, red);
    float e = expf(zn - m);
    float se = blockSum<8>(e, red);
    g_partial[sh * NOUT + tid] = e / se;
}

// ---------------- kTail: block per head — out_sm sum, gate, outputs ---------
__global__ __launch_bounds__(256) void kTail(
    const float* __restrict__ woo, float* __restrict__ out)
{
    int h = blockIdx.x, tid = threadIdx.x;
    __shared__ float red[8];

    float osm = 0.f;
#pragma unroll
    for (int s4 = 0; s4 < NSM; ++s4)
        osm += g_partial[(size_t)(s4 * NH + h) * NOUT + tid];

    float term = woo[(size_t)h * 2 * NOUT + tid] * g_lp[tid]
               + woo[(size_t)h * 2 * NOUT + NOUT + tid] * osm;
    float gl = blockSum<8>(term, red);
    float onoff = 1.f / (1.f + expf(-gl));

    float v = onoff * osm;
    out[tid * NH + h] = fmaxf(v, TINYF);
    float v2 = v * g_scalar_ho[h * NOUT + tid];
    out[NOUT * NH + tid * NH + h] = (fabsf(v2) <= TINYF) ? TINYF : v2;
}

// ---------------- launch -----------------------------------------------------
extern "C" void kernel_launch(void* const* d_in, const int* in_sizes, int n_in,
                              void* d_out, int out_size)
{
    const float* x    = (const float*)d_in[0];
    const float* last = (const float*)d_in[1];
    const float* qw   = (const float*)d_in[2];
    const float* w1   = (const float*)d_in[3];
    const float* g1   = (const float*)d_in[4];
    const float* b1   = (const float*)d_in[5];
    const float* w2   = (const float*)d_in[6];
    const float* g2   = (const float*)d_in[7];
    const float* b2   = (const float*)d_in[8];
    const float* ws   = (const float*)d_in[9];
    const float* woo  = (const float*)d_in[10];
    float* out = (float*)d_out;

    kA0<<<NH * 4, 256>>>(x, qw);
    kA1<<<NH * 8, 256>>>(w1);
    kA2<<<NH + 8, 512>>>(g1, b1, last);
    kZC<<<NSM * NH * 4 + 128, 256>>>(w2, ws);
    kP<<<NSM * NH, 256>>>(g2, b2);
    kTail<<<NH, 256>>>(woo, out);
}